// round 14
// baseline (speedup 1.0000x reference)
#include <cuda_runtime.h>
#include <cuda_fp16.h>
#include <cstdint>

#define NN 16384
#define DD 64
#define BLK 128           // tile is BLK x BLK
#define NTILES (NN / BLK) // 128
#define NPAIRS (NTILES * (NTILES + 1) / 2)   // 8256 upper-tri tiles
#define CHUNK 4
#define NCHUNKS ((NPAIRS + CHUNK - 1) / CHUNK)   // 2064
#define PREP_BLOCKS 1024

// ---------------- device scratch (no allocations allowed) ----------------
__device__ float  g_part8[NPAIRS * 8];          // per-(tile,warp) partials
__device__ float  g_pSa[PREP_BLOCKS], g_pSxi[PREP_BLOCKS], g_pSy[PREP_BLOCKS];
__device__ float  g_w[NN];
__device__ float  g_d2[NN];                     // exact fp32 diag: d_ii = x_i . x_i
__device__ __align__(128) __half g_h[NN * DD];  // fp16 x

// ---------------- helpers ----------------
__device__ __forceinline__ uint32_t smem_u32(const void* p) {
    uint32_t a;
    asm("{ .reg .u64 t; cvta.to.shared.u64 t, %1; cvt.u32.u64 %0, t; }"
        : "=r"(a) : "l"(p));
    return a;
}

#define CP_ASYNC16(dst, src) \
    asm volatile("cp.async.cg.shared.global [%0], [%1], 16;" \
                 :: "r"(dst), "l"(src) : "memory")
#define CP_COMMIT() asm volatile("cp.async.commit_group;" ::: "memory")
#define CP_WAIT0()  asm volatile("cp.async.wait_group 0;" ::: "memory")
#define CP_WAIT1()  asm volatile("cp.async.wait_group 1;" ::: "memory")

__device__ __forceinline__ void ldsm_x4(uint32_t& r0, uint32_t& r1,
                                        uint32_t& r2, uint32_t& r3, uint32_t addr) {
    asm volatile("ldmatrix.sync.aligned.m8n8.x4.shared.b16 {%0,%1,%2,%3}, [%4];"
                 : "=r"(r0), "=r"(r1), "=r"(r2), "=r"(r3) : "r"(addr));
}

__device__ __forceinline__ void mma_f16(float* c, const uint32_t* a, const uint32_t* b) {
    asm volatile(
        "mma.sync.aligned.m16n8k16.row.col.f32.f16.f16.f32 "
        "{%0,%1,%2,%3}, {%4,%5,%6,%7}, {%8,%9}, {%0,%1,%2,%3};"
        : "+f"(c[0]), "+f"(c[1]), "+f"(c[2]), "+f"(c[3])
        : "r"(a[0]), "r"(a[1]), "r"(a[2]), "r"(a[3]), "r"(b[0]), "r"(b[1]));
}

// scalars may be int32 or float32 bit patterns
__device__ __forceinline__ float scal_as_float(const int* p) {
    int v = *p;
    if (v < 0 || v >= 0x00800000) return __int_as_float(v);
    return (float)v;
}
__device__ __forceinline__ int scal_as_int(const int* p) {
    int v = *p;
    if (v < 0 || v >= 0x00800000) return (int)(__int_as_float(v) + 0.5f);
    return v;
}

// ---------------- prep: relu sums + w + fp16 cast + exact diag ----------------
// grid covers NN*DD/4 float4s exactly: 1024 blocks x 256 threads = 262144
__global__ __launch_bounds__(256)
void svm_prep_kernel(const float* __restrict__ x,
                     const float* __restrict__ alpha,
                     const float* __restrict__ xi,
                     const float* __restrict__ y) {
    const int i = blockIdx.x * 256 + threadIdx.x;

    // fp16 conversion: one float4 -> one uint2 (2x half2) per thread
    {
        float4 v = ((const float4*)x)[i];
        __half2 h0 = __floats2half2_rn(v.x, v.y);
        __half2 h1 = __floats2half2_rn(v.z, v.w);
        uint2 o;
        o.x = *(const uint32_t*)&h0;
        o.y = *(const uint32_t*)&h1;
        ((uint2*)g_h)[i] = o;
    }

    float a = 0.f, xr = 0.f, yv = 0.f;
    if (i < NN) {
        // exact diagonal
        const float4* row = (const float4*)(x + (size_t)i * DD);
        float s = 0.f;
        #pragma unroll
        for (int c = 0; c < 16; ++c) {
            float4 v = row[c];
            s += v.x * v.x + v.y * v.y + v.z * v.z + v.w * v.w;
        }
        g_d2[i] = s;

        a  = fmaxf(alpha[i], 0.f);
        xr = fmaxf(xi[i], 0.f);
        yv = y[i];
        g_w[i] = a * yv;
    }
    #pragma unroll
    for (int o = 16; o > 0; o >>= 1) {
        a  += __shfl_down_sync(0xffffffffu, a,  o);
        xr += __shfl_down_sync(0xffffffffu, xr, o);
        yv += __shfl_down_sync(0xffffffffu, yv, o);
    }
    __shared__ float rA[8], rX[8], rY[8];
    int wid = threadIdx.x >> 5, lid = threadIdx.x & 31;
    if (lid == 0) { rA[wid] = a; rX[wid] = xr; rY[wid] = yv; }
    __syncthreads();
    if (threadIdx.x == 0) {
        float sa = 0.f, sx = 0.f, sy = 0.f;
        #pragma unroll
        for (int w = 0; w < 8; ++w) { sa += rA[w]; sx += rX[w]; sy += rY[w]; }
        g_pSa[blockIdx.x]  = sa;
        g_pSxi[blockIdx.x] = sx;
        g_pSy[blockIdx.x]  = sy;
    }
}

// ---------------- main Gram kernel: CHUNK tiles/CTA, 3-stage ring -------------
// Per buffer: A tile 16KB + B tile 16KB. Vec region per buffer: wJ,yJ,wI,yI,d2
// (512B each). XOR chunk swizzle: off = row*128 + ((c16 ^ (row&7)) << 4)
// Safety: prefetch of tile t+2 (into buf (t+2)%3 == (t-1)%3) is issued AFTER
// iteration t's __syncthreads, which all warps reach only after finishing
// iteration t-1's reads of that buffer.
#define BUF_STRIDE 32768
#define OFF_VEC    (3 * BUF_STRIDE)
#define VEC_STRIDE 2560
#define SMEM_BYTES (3 * BUF_STRIDE + 3 * VEC_STRIDE + 256)

__global__ __launch_bounds__(256, 2)
void svm_quad_mma_kernel(const float* __restrict__ y,
                         const int* __restrict__ coeff_p,
                         const int* __restrict__ degree_p) {
    extern __shared__ char smem_raw[];
    const uint32_t raw = smem_u32(smem_raw);
    const uint32_t base = (raw + 127u) & ~127u;
    char* smem = smem_raw + (base - raw);

    const int tid = threadIdx.x;
    const int wid = tid >> 5;
    const int lid = tid & 31;
    const int wm  = wid & 3;   // 4 warps along M
    const int wn  = wid >> 2;  // 2 warps along N

    // ---- triangular decode of first tile in chunk ----
    const int idx0 = blockIdx.x * CHUNK;
    int I = (int)((2.0 * NTILES + 1.0
                   - sqrt((2.0 * NTILES + 1.0) * (2.0 * NTILES + 1.0) - 8.0 * idx0)) * 0.5);
    if (I > NTILES - 1) I = NTILES - 1;
    if (I < 0) I = 0;
    #pragma unroll 1
    while (I > 0 && (I * NTILES - (I * (I - 1)) / 2) > idx0) --I;
    #pragma unroll 1
    while (((I + 1) * NTILES - ((I + 1) * I) / 2) <= idx0) ++I;
    int J = I + (idx0 - (I * NTILES - (I * (I - 1)) / 2));
    const int ntile = (NPAIRS - idx0 < CHUNK) ? (NPAIRS - idx0) : CHUNK;

    #define ADV(I_, J_) do { if (++(J_) == NTILES) { ++(I_); (J_) = (I_); } } while (0)

    #define PREFETCH(I_, J_, cur_) do {                                          \
        const int pbi = (I_) * BLK, pbj = (J_) * BLK;                            \
        const char* srcA = (const char*)(g_h + (size_t)pbi * DD);                \
        const char* srcB = (const char*)(g_h + (size_t)pbj * DD);                \
        const uint32_t dA = base + (cur_) * BUF_STRIDE;                          \
        const uint32_t dB = dA + 16384;                                          \
        _Pragma("unroll")                                                        \
        for (int it = 0; it < 4; ++it) {                                         \
            int i2 = tid + it * 256;                                             \
            int row = i2 >> 3, c16 = i2 & 7;                                     \
            int sw = row * 128 + ((c16 ^ (row & 7)) << 4);                       \
            int lin = i2 * 16;                                                   \
            CP_ASYNC16(dA + sw, srcA + lin);                                     \
            CP_ASYNC16(dB + sw, srcB + lin);                                     \
        }                                                                        \
        if (tid < 160) {                                                         \
            const uint32_t dv = base + OFF_VEC + (cur_) * VEC_STRIDE;            \
            int v = tid >> 5, c = tid & 31;                                      \
            const float* vsrc;                                                   \
            if      (v == 0) vsrc = g_w  + pbj;                                  \
            else if (v == 1) vsrc = y    + pbj;                                  \
            else if (v == 2) vsrc = g_w  + pbi;                                  \
            else if (v == 3) vsrc = y    + pbi;                                  \
            else             vsrc = g_d2 + pbi;                                  \
            CP_ASYNC16(dv + v * 512 + c * 16, (const char*)(vsrc) + c * 16);     \
        }                                                                        \
        CP_COMMIT();                                                             \
    } while (0)

    // prologue: prefetch tiles 0 and 1
    PREFETCH(I, J, 0);
    int Ip = I, Jp = J;
    if (ntile > 1) { ADV(Ip, Jp); PREFETCH(Ip, Jp, 1); }

    // per-lane ldmatrix address components (k16 frag mapping)
    const int q   = lid >> 3;
    const int seg = lid & 7;
    const int rowA0 = wm * 32 + seg + ((q & 1) << 3);
    const int chA   = q >> 1;
    const int rowB0 = wn * 64 + seg + ((q >> 1) << 3);
    const int chB   = q & 1;
    const int rBase = wm * 32 + (lid >> 2);
    const int cBase = wn * 64 + 2 * (lid & 3);

    const float coeff = scal_as_float(coeff_p);
    const int   deg   = scal_as_int(degree_p);

    #pragma unroll 1
    for (int t = 0; t < ntile; ++t) {
        const int cur = t % 3;
        const bool offdiag = (I != J);

        // wait for tile t's group, then the sole per-tile barrier
        if (t + 1 < ntile) CP_WAIT1(); else CP_WAIT0();
        __syncthreads();

        // prefetch tile t+2 (safe: all warps have finished reading this buffer)
        if (t + 2 < ntile) {
            ADV(Ip, Jp);
            PREFETCH(Ip, Jp, (t + 2) % 3);
        }

        const uint32_t aB = base + cur * BUF_STRIDE;
        const uint32_t bB = aB + 16384;
        const char* vecp = smem + OFF_VEC + cur * VEC_STRIDE;
        const float* s_wJ = (const float*)(vecp);
        const float* s_yJ = (const float*)(vecp + 512);
        const float* s_wI = (const float*)(vecp + 1024);
        const float* s_yI = (const float*)(vecp + 1536);
        const float* s_d2 = (const float*)(vecp + 2048);

        float accf[2][8][4];
        #pragma unroll
        for (int am = 0; am < 2; ++am)
            #pragma unroll
            for (int bn = 0; bn < 8; ++bn)
                #pragma unroll
                for (int r = 0; r < 4; ++r) accf[am][bn][r] = 0.f;

        // ---- mainloop: single fp16 pass, K=64 (4 ks of 16) ----
        #pragma unroll
        for (int ks = 0; ks < 4; ++ks) {
            uint32_t af[2][4];
            #pragma unroll
            for (int am = 0; am < 2; ++am) {
                int row = rowA0 + am * 16;
                int ch  = (chA + 2 * ks) ^ (row & 7);
                ldsm_x4(af[am][0], af[am][1], af[am][2], af[am][3],
                        aB + row * 128 + (ch << 4));
            }
            uint32_t bf[8][2];
            #pragma unroll
            for (int bn2 = 0; bn2 < 4; ++bn2) {
                int row = rowB0 + bn2 * 16;
                int ch  = (chB + 2 * ks) ^ (row & 7);
                ldsm_x4(bf[bn2 * 2][0], bf[bn2 * 2][1],
                        bf[bn2 * 2 + 1][0], bf[bn2 * 2 + 1][1],
                        bB + row * 128 + (ch << 4));
            }
            #pragma unroll
            for (int am = 0; am < 2; ++am)
                #pragma unroll
                for (int bn = 0; bn < 8; ++bn)
                    mma_f16(accf[am][bn], af[am], bf[bn]);
        }

        // ---- exact diagonal patch (diag tiles only) ----
        if (!offdiag) {
            #pragma unroll
            for (int am = 0; am < 2; ++am)
                #pragma unroll
                for (int bn = 0; bn < 8; ++bn)
                    #pragma unroll
                    for (int r = 0; r < 4; ++r) {
                        int rl = rBase + am * 16 + ((r >> 1) << 3);
                        int cl = cBase + bn * 8 + (r & 1);
                        if (rl == cl) accf[am][bn][r] = s_d2[rl];
                    }
        }

        // ---- epilogue ----
        float part = 0.f;
        #pragma unroll
        for (int am = 0; am < 2; ++am) {
            const int r0i = rBase + am * 16;
            const float yr0 = s_yI[r0i],     yr1 = s_yI[r0i + 8];
            const float wr0 = s_wI[r0i],     wr1 = s_wI[r0i + 8];
            float s0w = 0.f, s1w = 0.f;
            float s0y = 0.f, s1y = 0.f;
            #pragma unroll
            for (int bn = 0; bn < 8; ++bn) {
                const int c0i = cBase + bn * 8;
                const float wc0 = s_wJ[c0i], wc1 = s_wJ[c0i + 1];
                const float yc0 = s_yJ[c0i], yc1 = s_yJ[c0i + 1];
                float k0, k1, k2, k3;
                if (deg == 3) {
                    float v0 = accf[am][bn][0] + coeff;
                    float v1 = accf[am][bn][1] + coeff;
                    float v2 = accf[am][bn][2] + coeff;
                    float v3 = accf[am][bn][3] + coeff;
                    k0 = v0 * v0 * v0; k1 = v1 * v1 * v1;
                    k2 = v2 * v2 * v2; k3 = v3 * v3 * v3;
                } else {
                    float v[4], kk[4];
                    #pragma unroll
                    for (int r = 0; r < 4; ++r) {
                        v[r] = accf[am][bn][r] + coeff;
                        float p = 1.f;
                        for (int d = 0; d < deg; ++d) p *= v[r];
                        kk[r] = p;
                    }
                    k0 = kk[0]; k1 = kk[1]; k2 = kk[2]; k3 = kk[3];
                }
                s0w = fmaf(wc0, k0, s0w); s0w = fmaf(wc1, k1, s0w);
                s1w = fmaf(wc0, k2, s1w); s1w = fmaf(wc1, k3, s1w);
                s0y = fmaf(yc0, k0, s0y); s0y = fmaf(yc1, k1, s0y);
                s1y = fmaf(yc0, k2, s1y); s1y = fmaf(yc1, k3, s1y);
            }
            part = fmaf(yr0, s0w, part);
            part = fmaf(yr1, s1w, part);
            if (offdiag) {
                part = fmaf(wr0, s0y, part);
                part = fmaf(wr1, s1y, part);
            }
        }

        // ---- warp reduce -> per-(tile,warp) partial; no block barrier ----
        #pragma unroll
        for (int o = 16; o > 0; o >>= 1)
            part += __shfl_down_sync(0xffffffffu, part, o);
        if (lid == 0) g_part8[(idx0 + t) * 8 + wid] = part;

        ADV(I, J);
    }
    #undef PREFETCH
    #undef ADV
}

// ---------------- final reduction + loss ----------------
__global__ __launch_bounds__(1024)
void svm_fin_kernel(const float* __restrict__ b,
                    const int*   __restrict__ C_p,
                    const int*   __restrict__ lambd_p,
                    float* __restrict__ out) {
    const int tid = threadIdx.x;
    double q = 0.0;
    for (int i = tid; i < NPAIRS * 8; i += 1024) q += (double)g_part8[i];
    double sa = 0.0, sx = 0.0, sy = 0.0;
    if (tid < PREP_BLOCKS) {
        sa = (double)g_pSa[tid];
        sx = (double)g_pSxi[tid];
        sy = (double)g_pSy[tid];
    }
    #pragma unroll
    for (int o = 16; o > 0; o >>= 1) {
        q  += __shfl_down_sync(0xffffffffu, q,  o);
        sa += __shfl_down_sync(0xffffffffu, sa, o);
        sx += __shfl_down_sync(0xffffffffu, sx, o);
        sy += __shfl_down_sync(0xffffffffu, sy, o);
    }
    __shared__ double rq[32], ra[32], rx[32], ry[32];
    int wid = tid >> 5, lid = tid & 31;
    if (lid == 0) { rq[wid] = q; ra[wid] = sa; rx[wid] = sx; ry[wid] = sy; }
    __syncthreads();
    if (tid == 0) {
        double Q = 0, Sa = 0, Sxi = 0, Sy = 0;
        #pragma unroll
        for (int w = 0; w < 32; ++w) {
            Q += rq[w]; Sa += ra[w]; Sxi += rx[w]; Sy += ry[w];
        }
        double C  = (double)scal_as_float(C_p);
        double la = (double)scal_as_float(lambd_p);
        double loss = 0.5 * Sa + C * Sxi
                    + la * ((Q + (double)b[0] * Sy + Sxi) / (double)NN - 1.0);
        out[0] = (float)loss;
    }
}

// ---------------- launch ----------------
extern "C" void kernel_launch(void* const* d_in, const int* in_sizes, int n_in,
                              void* d_out, int out_size) {
    const float* x      = (const float*)d_in[0];
    const float* y      = (const float*)d_in[1];
    const float* alpha  = (const float*)d_in[2];
    const float* xi     = (const float*)d_in[3];
    const float* b      = (const float*)d_in[4];
    const int*   coeff  = (const int*)d_in[5];
    const int*   degree = (const int*)d_in[6];
    const int*   Cc     = (const int*)d_in[7];
    const int*   lambd  = (const int*)d_in[8];
    float* out = (float*)d_out;

    static bool attr_set = false;
    if (!attr_set) {
        cudaFuncSetAttribute(svm_quad_mma_kernel,
                             cudaFuncAttributeMaxDynamicSharedMemorySize, SMEM_BYTES);
        attr_set = true;
    }

    svm_prep_kernel<<<PREP_BLOCKS, 256>>>(x, alpha, xi, y);
    svm_quad_mma_kernel<<<NCHUNKS, 256, SMEM_BYTES>>>(y, coeff, degree);
    svm_fin_kernel<<<1, 1024>>>(b, Cc, lambd, out);
}

// round 15
// speedup vs baseline: 1.3348x; 1.3348x over previous
#include <cuda_runtime.h>
#include <cuda_fp16.h>
#include <cstdint>

#define NN 16384
#define DD 64
#define BLK 128           // tile is BLK x BLK
#define NTILES (NN / BLK) // 128
#define NPAIRS (NTILES * (NTILES + 1) / 2)   // 8256 upper-tri tiles
#define CHUNK 4
#define NCHUNKS ((NPAIRS + CHUNK - 1) / CHUNK)   // 2064
#define PREP_BLOCKS 1024

// ---------------- device scratch (no allocations allowed) ----------------
__device__ float  g_part[NPAIRS];
__device__ float  g_pSa[PREP_BLOCKS], g_pSxi[PREP_BLOCKS], g_pSy[PREP_BLOCKS];
__device__ float  g_w[NN];
__device__ float  g_d2[NN];                     // exact fp32 diag: d_ii = x_i . x_i
__device__ __align__(128) __half g_h[NN * DD];  // fp16 x

// ---------------- helpers ----------------
__device__ __forceinline__ uint32_t smem_u32(const void* p) {
    uint32_t a;
    asm("{ .reg .u64 t; cvta.to.shared.u64 t, %1; cvt.u32.u64 %0, t; }"
        : "=r"(a) : "l"(p));
    return a;
}

#define CP_ASYNC16(dst, src) \
    asm volatile("cp.async.cg.shared.global [%0], [%1], 16;" \
                 :: "r"(dst), "l"(src) : "memory")
#define CP_COMMIT() asm volatile("cp.async.commit_group;" ::: "memory")
#define CP_WAIT0()  asm volatile("cp.async.wait_group 0;" ::: "memory")
#define CP_WAIT1()  asm volatile("cp.async.wait_group 1;" ::: "memory")

__device__ __forceinline__ void ldsm_x4(uint32_t& r0, uint32_t& r1,
                                        uint32_t& r2, uint32_t& r3, uint32_t addr) {
    asm volatile("ldmatrix.sync.aligned.m8n8.x4.shared.b16 {%0,%1,%2,%3}, [%4];"
                 : "=r"(r0), "=r"(r1), "=r"(r2), "=r"(r3) : "r"(addr));
}

__device__ __forceinline__ void mma_f16(float* c, const uint32_t* a, const uint32_t* b) {
    asm volatile(
        "mma.sync.aligned.m16n8k16.row.col.f32.f16.f16.f32 "
        "{%0,%1,%2,%3}, {%4,%5,%6,%7}, {%8,%9}, {%0,%1,%2,%3};"
        : "+f"(c[0]), "+f"(c[1]), "+f"(c[2]), "+f"(c[3])
        : "r"(a[0]), "r"(a[1]), "r"(a[2]), "r"(a[3]), "r"(b[0]), "r"(b[1]));
}

// scalars may be int32 or float32 bit patterns
__device__ __forceinline__ float scal_as_float(const int* p) {
    int v = *p;
    if (v < 0 || v >= 0x00800000) return __int_as_float(v);
    return (float)v;
}
__device__ __forceinline__ int scal_as_int(const int* p) {
    int v = *p;
    if (v < 0 || v >= 0x00800000) return (int)(__int_as_float(v) + 0.5f);
    return v;
}

// ---------------- prep: fp16 cast + fused exact diag + relu sums --------------
// grid covers NN*DD/4 float4s exactly: 1024 blocks x 256 threads = 262144.
// 16 consecutive threads cover one row (DD=64 = 16 float4s), so the row's
// |x|^2 is a 16-lane segmented shuffle reduce of per-thread sums of squares.
__global__ __launch_bounds__(256)
void svm_prep_kernel(const float* __restrict__ x,
                     const float* __restrict__ alpha,
                     const float* __restrict__ xi,
                     const float* __restrict__ y) {
    const int i = blockIdx.x * 256 + threadIdx.x;

    // fp16 conversion + per-thread sum of squares
    float s;
    {
        float4 v = ((const float4*)x)[i];
        __half2 h0 = __floats2half2_rn(v.x, v.y);
        __half2 h1 = __floats2half2_rn(v.z, v.w);
        uint2 o;
        o.x = *(const uint32_t*)&h0;
        o.y = *(const uint32_t*)&h1;
        ((uint2*)g_h)[i] = o;
        s = v.x * v.x + v.y * v.y + v.z * v.z + v.w * v.w;
    }
    // 16-lane segment reduce (width=16 keeps segments independent)
    #pragma unroll
    for (int o = 8; o > 0; o >>= 1)
        s += __shfl_down_sync(0xffffffffu, s, o, 16);
    if ((threadIdx.x & 15) == 0)
        g_d2[i >> 4] = s;

    float a = 0.f, xr = 0.f, yv = 0.f;
    if (i < NN) {
        a  = fmaxf(alpha[i], 0.f);
        xr = fmaxf(xi[i], 0.f);
        yv = y[i];
        g_w[i] = a * yv;
    }
    #pragma unroll
    for (int o = 16; o > 0; o >>= 1) {
        a  += __shfl_down_sync(0xffffffffu, a,  o);
        xr += __shfl_down_sync(0xffffffffu, xr, o);
        yv += __shfl_down_sync(0xffffffffu, yv, o);
    }
    __shared__ float rA[8], rX[8], rY[8];
    int wid = threadIdx.x >> 5, lid = threadIdx.x & 31;
    if (lid == 0) { rA[wid] = a; rX[wid] = xr; rY[wid] = yv; }
    __syncthreads();
    if (threadIdx.x == 0) {
        float sa = 0.f, sx = 0.f, sy = 0.f;
        #pragma unroll
        for (int w = 0; w < 8; ++w) { sa += rA[w]; sx += rX[w]; sy += rY[w]; }
        g_pSa[blockIdx.x]  = sa;
        g_pSxi[blockIdx.x] = sx;
        g_pSy[blockIdx.x]  = sy;
    }
}

// ---------------- main Gram kernel: R10 structure (proven 102.9us) ------------
// CHUNK tiles/CTA, double-buffered, prefetch-before-wait, two barriers/tile.
// Per buffer: A tile 16KB, B tile 16KB. Vec region per buffer: wJ,yJ,wI,yI,d2
// (512B each). XOR chunk swizzle: off = row*128 + ((c16 ^ (row&7)) << 4)
#define BUF_STRIDE 32768
#define OFF_VEC    65536
#define VEC_STRIDE 2560
#define SMEM_BYTES (65536 + 2 * VEC_STRIDE + 256)

__global__ __launch_bounds__(256, 2)
void svm_quad_mma_kernel(const float* __restrict__ y,
                         const int* __restrict__ coeff_p,
                         const int* __restrict__ degree_p) {
    extern __shared__ char smem_raw[];
    const uint32_t raw = smem_u32(smem_raw);
    const uint32_t base = (raw + 127u) & ~127u;
    char* smem = smem_raw + (base - raw);

    const int tid = threadIdx.x;
    const int wid = tid >> 5;
    const int lid = tid & 31;
    const int wm  = wid & 3;   // 4 warps along M
    const int wn  = wid >> 2;  // 2 warps along N

    // ---- triangular decode of first tile in chunk ----
    const int idx0 = blockIdx.x * CHUNK;
    int I = (int)((2.0 * NTILES + 1.0
                   - sqrt((2.0 * NTILES + 1.0) * (2.0 * NTILES + 1.0) - 8.0 * idx0)) * 0.5);
    if (I > NTILES - 1) I = NTILES - 1;
    if (I < 0) I = 0;
    #pragma unroll 1
    while (I > 0 && (I * NTILES - (I * (I - 1)) / 2) > idx0) --I;
    #pragma unroll 1
    while (((I + 1) * NTILES - ((I + 1) * I) / 2) <= idx0) ++I;
    int J = I + (idx0 - (I * NTILES - (I * (I - 1)) / 2));
    const int ntile = (NPAIRS - idx0 < CHUNK) ? (NPAIRS - idx0) : CHUNK;

    #define PREFETCH(I_, J_, cur_) do {                                          \
        const int pbi = (I_) * BLK, pbj = (J_) * BLK;                            \
        const char* srcA = (const char*)(g_h + (size_t)pbi * DD);                \
        const char* srcB = (const char*)(g_h + (size_t)pbj * DD);                \
        const uint32_t dA = base + (cur_) * BUF_STRIDE;                          \
        const uint32_t dB = dA + 16384;                                          \
        _Pragma("unroll")                                                        \
        for (int it = 0; it < 4; ++it) {                                         \
            int i2 = tid + it * 256;                                             \
            int row = i2 >> 3, c16 = i2 & 7;                                     \
            int sw = row * 128 + ((c16 ^ (row & 7)) << 4);                       \
            int lin = i2 * 16;                                                   \
            CP_ASYNC16(dA + sw, srcA + lin);                                     \
            CP_ASYNC16(dB + sw, srcB + lin);                                     \
        }                                                                        \
        if (tid < 160) {                                                         \
            const uint32_t dv = base + OFF_VEC + (cur_) * VEC_STRIDE;            \
            int v = tid >> 5, c = tid & 31;                                      \
            const float* vsrc;                                                   \
            if      (v == 0) vsrc = g_w  + pbj;                                  \
            else if (v == 1) vsrc = y    + pbj;                                  \
            else if (v == 2) vsrc = g_w  + pbi;                                  \
            else if (v == 3) vsrc = y    + pbi;                                  \
            else             vsrc = g_d2 + pbi;                                  \
            CP_ASYNC16(dv + v * 512 + c * 16, (const char*)(vsrc) + c * 16);     \
        }                                                                        \
        CP_COMMIT();                                                             \
    } while (0)

    PREFETCH(I, J, 0);

    // per-lane ldmatrix address components (k16 frag mapping)
    const int q   = lid >> 3;
    const int seg = lid & 7;
    const int rowA0 = wm * 32 + seg + ((q & 1) << 3);
    const int chA   = q >> 1;
    const int rowB0 = wn * 64 + seg + ((q >> 1) << 3);
    const int chB   = q & 1;
    const int rBase = wm * 32 + (lid >> 2);
    const int cBase = wn * 64 + 2 * (lid & 3);

    const float coeff = scal_as_float(coeff_p);
    const int   deg   = scal_as_int(degree_p);

    #pragma unroll 1
    for (int t = 0; t < ntile; ++t) {
        const int cur = t & 1;
        const bool offdiag = (I != J);

        // prefetch next tile into the other buffer
        int In = I, Jn = J + 1;
        if (Jn == NTILES) { ++In; Jn = In; }
        if (t + 1 < ntile) {
            PREFETCH(In, Jn, 1 - cur);
            CP_WAIT1();
        } else {
            CP_WAIT0();
        }
        __syncthreads();

        const uint32_t aB = base + cur * BUF_STRIDE;
        const uint32_t bB = aB + 16384;
        const char* vecp = smem + OFF_VEC + cur * VEC_STRIDE;
        const float* s_wJ = (const float*)(vecp);
        const float* s_yJ = (const float*)(vecp + 512);
        const float* s_wI = (const float*)(vecp + 1024);
        const float* s_yI = (const float*)(vecp + 1536);
        const float* s_d2 = (const float*)(vecp + 2048);

        float accf[2][8][4];
        #pragma unroll
        for (int am = 0; am < 2; ++am)
            #pragma unroll
            for (int bn = 0; bn < 8; ++bn)
                #pragma unroll
                for (int r = 0; r < 4; ++r) accf[am][bn][r] = 0.f;

        // ---- mainloop: single fp16 pass, K=64 (4 ks of 16) ----
        #pragma unroll
        for (int ks = 0; ks < 4; ++ks) {
            uint32_t af[2][4];
            #pragma unroll
            for (int am = 0; am < 2; ++am) {
                int row = rowA0 + am * 16;
                int ch  = (chA + 2 * ks) ^ (row & 7);
                ldsm_x4(af[am][0], af[am][1], af[am][2], af[am][3],
                        aB + row * 128 + (ch << 4));
            }
            uint32_t bf[8][2];
            #pragma unroll
            for (int bn2 = 0; bn2 < 4; ++bn2) {
                int row = rowB0 + bn2 * 16;
                int ch  = (chB + 2 * ks) ^ (row & 7);
                ldsm_x4(bf[bn2 * 2][0], bf[bn2 * 2][1],
                        bf[bn2 * 2 + 1][0], bf[bn2 * 2 + 1][1],
                        bB + row * 128 + (ch << 4));
            }
            #pragma unroll
            for (int am = 0; am < 2; ++am)
                #pragma unroll
                for (int bn = 0; bn < 8; ++bn)
                    mma_f16(accf[am][bn], af[am], bf[bn]);
        }

        // ---- exact diagonal patch (diag tiles only) ----
        if (!offdiag) {
            #pragma unroll
            for (int am = 0; am < 2; ++am)
                #pragma unroll
                for (int bn = 0; bn < 8; ++bn)
                    #pragma unroll
                    for (int r = 0; r < 4; ++r) {
                        int rl = rBase + am * 16 + ((r >> 1) << 3);
                        int cl = cBase + bn * 8 + (r & 1);
                        if (rl == cl) accf[am][bn][r] = s_d2[rl];
                    }
        }

        // ---- epilogue ----
        float part = 0.f;
        #pragma unroll
        for (int am = 0; am < 2; ++am) {
            const int r0i = rBase + am * 16;
            const float yr0 = s_yI[r0i],     yr1 = s_yI[r0i + 8];
            const float wr0 = s_wI[r0i],     wr1 = s_wI[r0i + 8];
            float s0w = 0.f, s1w = 0.f;
            float s0y = 0.f, s1y = 0.f;
            #pragma unroll
            for (int bn = 0; bn < 8; ++bn) {
                const int c0i = cBase + bn * 8;
                const float wc0 = s_wJ[c0i], wc1 = s_wJ[c0i + 1];
                const float yc0 = s_yJ[c0i], yc1 = s_yJ[c0i + 1];
                float k0, k1, k2, k3;
                if (deg == 3) {
                    float v0 = accf[am][bn][0] + coeff;
                    float v1 = accf[am][bn][1] + coeff;
                    float v2 = accf[am][bn][2] + coeff;
                    float v3 = accf[am][bn][3] + coeff;
                    k0 = v0 * v0 * v0; k1 = v1 * v1 * v1;
                    k2 = v2 * v2 * v2; k3 = v3 * v3 * v3;
                } else {
                    float v[4], kk[4];
                    #pragma unroll
                    for (int r = 0; r < 4; ++r) {
                        v[r] = accf[am][bn][r] + coeff;
                        float p = 1.f;
                        for (int d = 0; d < deg; ++d) p *= v[r];
                        kk[r] = p;
                    }
                    k0 = kk[0]; k1 = kk[1]; k2 = kk[2]; k3 = kk[3];
                }
                s0w = fmaf(wc0, k0, s0w); s0w = fmaf(wc1, k1, s0w);
                s1w = fmaf(wc0, k2, s1w); s1w = fmaf(wc1, k3, s1w);
                s0y = fmaf(yc0, k0, s0y); s0y = fmaf(yc1, k1, s0y);
                s1y = fmaf(yc0, k2, s1y); s1y = fmaf(yc1, k3, s1y);
            }
            part = fmaf(yr0, s0w, part);
            part = fmaf(yr1, s1w, part);
            if (offdiag) {
                part = fmaf(wr0, s0y, part);
                part = fmaf(wr1, s1y, part);
            }
        }

        // ---- block reduce -> per-CTA partial (R10 structure) ----
        #pragma unroll
        for (int o = 16; o > 0; o >>= 1)
            part += __shfl_down_sync(0xffffffffu, part, o);
        __shared__ float red[8];
        if (lid == 0) red[wid] = part;
        __syncthreads();   // protects red[] AND buffer reads before next refill
        if (tid == 0) {
            float s = 0.f;
            #pragma unroll
            for (int w = 0; w < 8; ++w) s += red[w];
            g_part[idx0 + t] = s;
        }
        I = In; J = Jn;
    }
    #undef PREFETCH
}

// ---------------- final reduction + loss ----------------
__global__ __launch_bounds__(1024)
void svm_fin_kernel(const float* __restrict__ b,
                    const int*   __restrict__ C_p,
                    const int*   __restrict__ lambd_p,
                    float* __restrict__ out) {
    const int tid = threadIdx.x;
    double q = 0.0;
    for (int i = tid; i < NPAIRS; i += 1024) q += (double)g_part[i];
    double sa = 0.0, sx = 0.0, sy = 0.0;
    if (tid < PREP_BLOCKS) {
        sa = (double)g_pSa[tid];
        sx = (double)g_pSxi[tid];
        sy = (double)g_pSy[tid];
    }
    #pragma unroll
    for (int o = 16; o > 0; o >>= 1) {
        q  += __shfl_down_sync(0xffffffffu, q,  o);
        sa += __shfl_down_sync(0xffffffffu, sa, o);
        sx += __shfl_down_sync(0xffffffffu, sx, o);
        sy += __shfl_down_sync(0xffffffffu, sy, o);
    }
    __shared__ double rq[32], ra[32], rx[32], ry[32];
    int wid = tid >> 5, lid = tid & 31;
    if (lid == 0) { rq[wid] = q; ra[wid] = sa; rx[wid] = sx; ry[wid] = sy; }
    __syncthreads();
    if (tid == 0) {
        double Q = 0, Sa = 0, Sxi = 0, Sy = 0;
        #pragma unroll
        for (int w = 0; w < 32; ++w) {
            Q += rq[w]; Sa += ra[w]; Sxi += rx[w]; Sy += ry[w];
        }
        double C  = (double)scal_as_float(C_p);
        double la = (double)scal_as_float(lambd_p);
        double loss = 0.5 * Sa + C * Sxi
                    + la * ((Q + (double)b[0] * Sy + Sxi) / (double)NN - 1.0);
        out[0] = (float)loss;
    }
}

// ---------------- launch ----------------
extern "C" void kernel_launch(void* const* d_in, const int* in_sizes, int n_in,
                              void* d_out, int out_size) {
    const float* x      = (const float*)d_in[0];
    const float* y      = (const float*)d_in[1];
    const float* alpha  = (const float*)d_in[2];
    const float* xi     = (const float*)d_in[3];
    const float* b      = (const float*)d_in[4];
    const int*   coeff  = (const int*)d_in[5];
    const int*   degree = (const int*)d_in[6];
    const int*   Cc     = (const int*)d_in[7];
    const int*   lambd  = (const int*)d_in[8];
    float* out = (float*)d_out;

    static bool attr_set = false;
    if (!attr_set) {
        cudaFuncSetAttribute(svm_quad_mma_kernel,
                             cudaFuncAttributeMaxDynamicSharedMemorySize, SMEM_BYTES);
        attr_set = true;
    }

    svm_prep_kernel<<<PREP_BLOCKS, 256>>>(x, alpha, xi, y);
    svm_quad_mma_kernel<<<NCHUNKS, 256, SMEM_BYTES>>>(y, coeff, degree);
    svm_fin_kernel<<<1, 1024>>>(b, Cc, lambd, out);
}

// round 16
// speedup vs baseline: 1.4073x; 1.0543x over previous
#include <cuda_runtime.h>
#include <cuda_fp16.h>
#include <cstdint>

#define NN 16384
#define DD 64
#define BLK 128           // tile is BLK x BLK
#define NTILES (NN / BLK) // 128
#define NPAIRS (NTILES * (NTILES + 1) / 2)   // 8256 upper-tri tiles
#define CHUNK 4
#define NCHUNKS ((NPAIRS + CHUNK - 1) / CHUNK)   // 2064
#define PREP_BLOCKS 1024

// ---------------- device scratch (no allocations allowed) ----------------
__device__ float  g_part[NPAIRS];
__device__ float  g_pSa[PREP_BLOCKS], g_pSxi[PREP_BLOCKS], g_pSy[PREP_BLOCKS];
__device__ float  g_w[NN];
__device__ float  g_d2[NN];                     // exact fp32 diag: d_ii = x_i . x_i
__device__ __align__(128) __half g_h[NN * DD];  // fp16 x

// ---------------- helpers ----------------
__device__ __forceinline__ uint32_t smem_u32(const void* p) {
    uint32_t a;
    asm("{ .reg .u64 t; cvta.to.shared.u64 t, %1; cvt.u32.u64 %0, t; }"
        : "=r"(a) : "l"(p));
    return a;
}

#define CP_ASYNC16(dst, src) \
    asm volatile("cp.async.cg.shared.global [%0], [%1], 16;" \
                 :: "r"(dst), "l"(src) : "memory")
#define CP_COMMIT() asm volatile("cp.async.commit_group;" ::: "memory")
#define CP_WAIT0()  asm volatile("cp.async.wait_group 0;" ::: "memory")
#define CP_WAIT1()  asm volatile("cp.async.wait_group 1;" ::: "memory")

__device__ __forceinline__ void ldsm_x4(uint32_t& r0, uint32_t& r1,
                                        uint32_t& r2, uint32_t& r3, uint32_t addr) {
    asm volatile("ldmatrix.sync.aligned.m8n8.x4.shared.b16 {%0,%1,%2,%3}, [%4];"
                 : "=r"(r0), "=r"(r1), "=r"(r2), "=r"(r3) : "r"(addr));
}

__device__ __forceinline__ void mma_f16(float* c, const uint32_t* a, const uint32_t* b) {
    asm volatile(
        "mma.sync.aligned.m16n8k16.row.col.f32.f16.f16.f32 "
        "{%0,%1,%2,%3}, {%4,%5,%6,%7}, {%8,%9}, {%0,%1,%2,%3};"
        : "+f"(c[0]), "+f"(c[1]), "+f"(c[2]), "+f"(c[3])
        : "r"(a[0]), "r"(a[1]), "r"(a[2]), "r"(a[3]), "r"(b[0]), "r"(b[1]));
}

// first-k variant: C = 0 (kills per-tile accumulator zero-init)
__device__ __forceinline__ void mma_f16_z(float* c, const uint32_t* a, const uint32_t* b) {
    asm volatile(
        "mma.sync.aligned.m16n8k16.row.col.f32.f16.f16.f32 "
        "{%0,%1,%2,%3}, {%4,%5,%6,%7}, {%8,%9}, {%10,%10,%10,%10};"
        : "=f"(c[0]), "=f"(c[1]), "=f"(c[2]), "=f"(c[3])
        : "r"(a[0]), "r"(a[1]), "r"(a[2]), "r"(a[3]), "r"(b[0]), "r"(b[1]),
          "f"(0.f));
}

// packed f32x2 ops (PTX ISA 8.6, sm_100+; NOT 'a'-gated)
#define PACK2(d, lo, hi) \
    asm("mov.b64 %0, {%1, %2};" : "=l"(d) : "f"(lo), "f"(hi))
#define UNPACK2(lo, hi, s) \
    asm("mov.b64 {%0, %1}, %2;" : "=f"(lo), "=f"(hi) : "l"(s))
#define ADD2(d, a, b) \
    asm("add.rn.f32x2 %0, %1, %2;" : "=l"(d) : "l"(a), "l"(b))
#define MUL2(d, a, b) \
    asm("mul.rn.f32x2 %0, %1, %2;" : "=l"(d) : "l"(a), "l"(b))
#define FMA2(d, a, b, c) \
    asm("fma.rn.f32x2 %0, %1, %2, %3;" : "=l"(d) : "l"(a), "l"(b), "l"(c))

// scalars may be int32 or float32 bit patterns
__device__ __forceinline__ float scal_as_float(const int* p) {
    int v = *p;
    if (v < 0 || v >= 0x00800000) return __int_as_float(v);
    return (float)v;
}
__device__ __forceinline__ int scal_as_int(const int* p) {
    int v = *p;
    if (v < 0 || v >= 0x00800000) return (int)(__int_as_float(v) + 0.5f);
    return v;
}

// ---------------- prep: fp16 cast + fused exact diag + relu sums --------------
__global__ __launch_bounds__(256)
void svm_prep_kernel(const float* __restrict__ x,
                     const float* __restrict__ alpha,
                     const float* __restrict__ xi,
                     const float* __restrict__ y) {
    const int i = blockIdx.x * 256 + threadIdx.x;

    float s;
    {
        float4 v = ((const float4*)x)[i];
        __half2 h0 = __floats2half2_rn(v.x, v.y);
        __half2 h1 = __floats2half2_rn(v.z, v.w);
        uint2 o;
        o.x = *(const uint32_t*)&h0;
        o.y = *(const uint32_t*)&h1;
        ((uint2*)g_h)[i] = o;
        s = v.x * v.x + v.y * v.y + v.z * v.z + v.w * v.w;
    }
    #pragma unroll
    for (int o = 8; o > 0; o >>= 1)
        s += __shfl_down_sync(0xffffffffu, s, o, 16);
    if ((threadIdx.x & 15) == 0)
        g_d2[i >> 4] = s;

    float a = 0.f, xr = 0.f, yv = 0.f;
    if (i < NN) {
        a  = fmaxf(alpha[i], 0.f);
        xr = fmaxf(xi[i], 0.f);
        yv = y[i];
        g_w[i] = a * yv;
    }
    #pragma unroll
    for (int o = 16; o > 0; o >>= 1) {
        a  += __shfl_down_sync(0xffffffffu, a,  o);
        xr += __shfl_down_sync(0xffffffffu, xr, o);
        yv += __shfl_down_sync(0xffffffffu, yv, o);
    }
    __shared__ float rA[8], rX[8], rY[8];
    int wid = threadIdx.x >> 5, lid = threadIdx.x & 31;
    if (lid == 0) { rA[wid] = a; rX[wid] = xr; rY[wid] = yv; }
    __syncthreads();
    if (threadIdx.x == 0) {
        float sa = 0.f, sx = 0.f, sy = 0.f;
        #pragma unroll
        for (int w = 0; w < 8; ++w) { sa += rA[w]; sx += rX[w]; sy += rY[w]; }
        g_pSa[blockIdx.x]  = sa;
        g_pSxi[blockIdx.x] = sx;
        g_pSy[blockIdx.x]  = sy;
    }
}

// ---------------- main Gram kernel: R10/R14 structure + packed epilogue -------
#define BUF_STRIDE 32768
#define OFF_VEC    65536
#define VEC_STRIDE 2560
#define SMEM_BYTES (65536 + 2 * VEC_STRIDE + 256)

__global__ __launch_bounds__(256, 2)
void svm_quad_mma_kernel(const float* __restrict__ y,
                         const int* __restrict__ coeff_p,
                         const int* __restrict__ degree_p) {
    extern __shared__ char smem_raw[];
    const uint32_t raw = smem_u32(smem_raw);
    const uint32_t base = (raw + 127u) & ~127u;
    char* smem = smem_raw + (base - raw);

    const int tid = threadIdx.x;
    const int wid = tid >> 5;
    const int lid = tid & 31;
    const int wm  = wid & 3;
    const int wn  = wid >> 2;

    // ---- triangular decode of first tile in chunk ----
    const int idx0 = blockIdx.x * CHUNK;
    int I = (int)((2.0 * NTILES + 1.0
                   - sqrt((2.0 * NTILES + 1.0) * (2.0 * NTILES + 1.0) - 8.0 * idx0)) * 0.5);
    if (I > NTILES - 1) I = NTILES - 1;
    if (I < 0) I = 0;
    #pragma unroll 1
    while (I > 0 && (I * NTILES - (I * (I - 1)) / 2) > idx0) --I;
    #pragma unroll 1
    while (((I + 1) * NTILES - ((I + 1) * I) / 2) <= idx0) ++I;
    int J = I + (idx0 - (I * NTILES - (I * (I - 1)) / 2));
    const int ntile = (NPAIRS - idx0 < CHUNK) ? (NPAIRS - idx0) : CHUNK;

    #define PREFETCH(I_, J_, cur_) do {                                          \
        const int pbi = (I_) * BLK, pbj = (J_) * BLK;                            \
        const char* srcA = (const char*)(g_h + (size_t)pbi * DD);                \
        const char* srcB = (const char*)(g_h + (size_t)pbj * DD);                \
        const uint32_t dA = base + (cur_) * BUF_STRIDE;                          \
        const uint32_t dB = dA + 16384;                                          \
        _Pragma("unroll")                                                        \
        for (int it = 0; it < 4; ++it) {                                         \
            int i2 = tid + it * 256;                                             \
            int row = i2 >> 3, c16 = i2 & 7;                                     \
            int sw = row * 128 + ((c16 ^ (row & 7)) << 4);                       \
            int lin = i2 * 16;                                                   \
            CP_ASYNC16(dA + sw, srcA + lin);                                     \
            CP_ASYNC16(dB + sw, srcB + lin);                                     \
        }                                                                        \
        if (tid < 160) {                                                         \
            const uint32_t dv = base + OFF_VEC + (cur_) * VEC_STRIDE;            \
            int v = tid >> 5, c = tid & 31;                                      \
            const float* vsrc;                                                   \
            if      (v == 0) vsrc = g_w  + pbj;                                  \
            else if (v == 1) vsrc = y    + pbj;                                  \
            else if (v == 2) vsrc = g_w  + pbi;                                  \
            else if (v == 3) vsrc = y    + pbi;                                  \
            else             vsrc = g_d2 + pbi;                                  \
            CP_ASYNC16(dv + v * 512 + c * 16, (const char*)(vsrc) + c * 16);     \
        }                                                                        \
        CP_COMMIT();                                                             \
    } while (0)

    PREFETCH(I, J, 0);

    const int q   = lid >> 3;
    const int seg = lid & 7;
    const int rowA0 = wm * 32 + seg + ((q & 1) << 3);
    const int chA   = q >> 1;
    const int rowB0 = wn * 64 + seg + ((q >> 1) << 3);
    const int chB   = q & 1;
    const int rBase = wm * 32 + (lid >> 2);
    const int cBase = wn * 64 + 2 * (lid & 3);

    const float coeff = scal_as_float(coeff_p);
    const int   deg   = scal_as_int(degree_p);
    uint64_t coeff2;
    PACK2(coeff2, coeff, coeff);

    #pragma unroll 1
    for (int t = 0; t < ntile; ++t) {
        const int cur = t & 1;
        const bool offdiag = (I != J);

        int In = I, Jn = J + 1;
        if (Jn == NTILES) { ++In; Jn = In; }
        if (t + 1 < ntile) {
            PREFETCH(In, Jn, 1 - cur);
            CP_WAIT1();
        } else {
            CP_WAIT0();
        }
        __syncthreads();

        const uint32_t aB = base + cur * BUF_STRIDE;
        const uint32_t bB = aB + 16384;
        const char* vecp = smem + OFF_VEC + cur * VEC_STRIDE;
        const float* s_wJ = (const float*)(vecp);
        const float* s_yJ = (const float*)(vecp + 512);
        const float* s_wI = (const float*)(vecp + 1024);
        const float* s_yI = (const float*)(vecp + 1536);
        const float* s_d2 = (const float*)(vecp + 2048);

        float accf[2][8][4];

        // ---- mainloop: single fp16 pass, K=64; ks=0 writes C=0 ----
        #pragma unroll
        for (int ks = 0; ks < 4; ++ks) {
            uint32_t af[2][4];
            #pragma unroll
            for (int am = 0; am < 2; ++am) {
                int row = rowA0 + am * 16;
                int ch  = (chA + 2 * ks) ^ (row & 7);
                ldsm_x4(af[am][0], af[am][1], af[am][2], af[am][3],
                        aB + row * 128 + (ch << 4));
            }
            uint32_t bf[8][2];
            #pragma unroll
            for (int bn2 = 0; bn2 < 4; ++bn2) {
                int row = rowB0 + bn2 * 16;
                int ch  = (chB + 2 * ks) ^ (row & 7);
                ldsm_x4(bf[bn2 * 2][0], bf[bn2 * 2][1],
                        bf[bn2 * 2 + 1][0], bf[bn2 * 2 + 1][1],
                        bB + row * 128 + (ch << 4));
            }
            if (ks == 0) {
                #pragma unroll
                for (int am = 0; am < 2; ++am)
                    #pragma unroll
                    for (int bn = 0; bn < 8; ++bn)
                        mma_f16_z(accf[am][bn], af[am], bf[bn]);
            } else {
                #pragma unroll
                for (int am = 0; am < 2; ++am)
                    #pragma unroll
                    for (int bn = 0; bn < 8; ++bn)
                        mma_f16(accf[am][bn], af[am], bf[bn]);
            }
        }

        // ---- exact diagonal patch (diag tiles only) ----
        if (!offdiag) {
            #pragma unroll
            for (int am = 0; am < 2; ++am)
                #pragma unroll
                for (int bn = 0; bn < 8; ++bn)
                    #pragma unroll
                    for (int r = 0; r < 4; ++r) {
                        int rl = rBase + am * 16 + ((r >> 1) << 3);
                        int cl = cBase + bn * 8 + (r & 1);
                        if (rl == cl) accf[am][bn][r] = s_d2[rl];
                    }
        }

        // ---- epilogue ----
        float part = 0.f;
        #pragma unroll
        for (int am = 0; am < 2; ++am) {
            const int r0i = rBase + am * 16;
            const float yr0 = s_yI[r0i],     yr1 = s_yI[r0i + 8];
            const float wr0 = s_wI[r0i],     wr1 = s_wI[r0i + 8];
            if (deg == 3) {
                // packed f32x2: lanes = adjacent columns (c, c+1); weight
                // pairs load directly as 64-bit from smem (8B-aligned).
                uint64_t S0w = 0, S1w = 0, S0y = 0, S1y = 0;
                #pragma unroll
                for (int bn = 0; bn < 8; ++bn) {
                    const int c0i = cBase + bn * 8;
                    const uint64_t W01 = *(const uint64_t*)(s_wJ + c0i);
                    const uint64_t Y01 = *(const uint64_t*)(s_yJ + c0i);
                    uint64_t k01, k23, p, q01, q23;
                    PACK2(k01, accf[am][bn][0], accf[am][bn][1]);
                    PACK2(k23, accf[am][bn][2], accf[am][bn][3]);
                    ADD2(k01, k01, coeff2);
                    ADD2(k23, k23, coeff2);
                    MUL2(p, k01, k01);  MUL2(q01, p, k01);
                    MUL2(p, k23, k23);  MUL2(q23, p, k23);
                    FMA2(S0w, W01, q01, S0w);
                    FMA2(S1w, W01, q23, S1w);
                    FMA2(S0y, Y01, q01, S0y);
                    FMA2(S1y, Y01, q23, S1y);
                }
                float a0, a1;
                UNPACK2(a0, a1, S0w); float s0w = a0 + a1;
                UNPACK2(a0, a1, S1w); float s1w = a0 + a1;
                part = fmaf(yr0, s0w, part);
                part = fmaf(yr1, s1w, part);
                if (offdiag) {
                    UNPACK2(a0, a1, S0y); float s0y = a0 + a1;
                    UNPACK2(a0, a1, S1y); float s1y = a0 + a1;
                    part = fmaf(wr0, s0y, part);
                    part = fmaf(wr1, s1y, part);
                }
            } else {
                float s0w = 0.f, s1w = 0.f, s0y = 0.f, s1y = 0.f;
                #pragma unroll
                for (int bn = 0; bn < 8; ++bn) {
                    const int c0i = cBase + bn * 8;
                    const float wc0 = s_wJ[c0i], wc1 = s_wJ[c0i + 1];
                    const float yc0 = s_yJ[c0i], yc1 = s_yJ[c0i + 1];
                    float kk[4];
                    #pragma unroll
                    for (int r = 0; r < 4; ++r) {
                        float v = accf[am][bn][r] + coeff;
                        float p = 1.f;
                        for (int d = 0; d < deg; ++d) p *= v;
                        kk[r] = p;
                    }
                    s0w = fmaf(wc0, kk[0], s0w); s0w = fmaf(wc1, kk[1], s0w);
                    s1w = fmaf(wc0, kk[2], s1w); s1w = fmaf(wc1, kk[3], s1w);
                    s0y = fmaf(yc0, kk[0], s0y); s0y = fmaf(yc1, kk[1], s0y);
                    s1y = fmaf(yc0, kk[2], s1y); s1y = fmaf(yc1, kk[3], s1y);
                }
                part = fmaf(yr0, s0w, part);
                part = fmaf(yr1, s1w, part);
                if (offdiag) {
                    part = fmaf(wr0, s0y, part);
                    part = fmaf(wr1, s1y, part);
                }
            }
        }

        // ---- block reduce -> per-CTA partial (R10 structure) ----
        #pragma unroll
        for (int o = 16; o > 0; o >>= 1)
            part += __shfl_down_sync(0xffffffffu, part, o);
        __shared__ float red[8];
        if (lid == 0) red[wid] = part;
        __syncthreads();   // protects red[] AND buffer reads before next refill
        if (tid == 0) {
            float s = 0.f;
            #pragma unroll
            for (int w = 0; w < 8; ++w) s += red[w];
            g_part[idx0 + t] = s;
        }
        I = In; J = Jn;
    }
    #undef PREFETCH
}

// ---------------- final reduction + loss ----------------
__global__ __launch_bounds__(1024)
void svm_fin_kernel(const float* __restrict__ b,
                    const int*   __restrict__ C_p,
                    const int*   __restrict__ lambd_p,
                    float* __restrict__ out) {
    const int tid = threadIdx.x;
    double q = 0.0;
    for (int i = tid; i < NPAIRS; i += 1024) q += (double)g_part[i];
    double sa = 0.0, sx = 0.0, sy = 0.0;
    if (tid < PREP_BLOCKS) {
        sa = (double)g_pSa[tid];
        sx = (double)g_pSxi[tid];
        sy = (double)g_pSy[tid];
    }
    #pragma unroll
    for (int o = 16; o > 0; o >>= 1) {
        q  += __shfl_down_sync(0xffffffffu, q,  o);
        sa += __shfl_down_sync(0xffffffffu, sa, o);
        sx += __shfl_down_sync(0xffffffffu, sx, o);
        sy += __shfl_down_sync(0xffffffffu, sy, o);
    }
    __shared__ double rq[32], ra[32], rx[32], ry[32];
    int wid = tid >> 5, lid = tid & 31;
    if (lid == 0) { rq[wid] = q; ra[wid] = sa; rx[wid] = sx; ry[wid] = sy; }
    __syncthreads();
    if (tid == 0) {
        double Q = 0, Sa = 0, Sxi = 0, Sy = 0;
        #pragma unroll
        for (int w = 0; w < 32; ++w) {
            Q += rq[w]; Sa += ra[w]; Sxi += rx[w]; Sy += ry[w];
        }
        double C  = (double)scal_as_float(C_p);
        double la = (double)scal_as_float(lambd_p);
        double loss = 0.5 * Sa + C * Sxi
                    + la * ((Q + (double)b[0] * Sy + Sxi) / (double)NN - 1.0);
        out[0] = (float)loss;
    }
}

// ---------------- launch ----------------
extern "C" void kernel_launch(void* const* d_in, const int* in_sizes, int n_in,
                              void* d_out, int out_size) {
    const float* x      = (const float*)d_in[0];
    const float* y      = (const float*)d_in[1];
    const float* alpha  = (const float*)d_in[2];
    const float* xi     = (const float*)d_in[3];
    const float* b      = (const float*)d_in[4];
    const int*   coeff  = (const int*)d_in[5];
    const int*   degree = (const int*)d_in[6];
    const int*   Cc     = (const int*)d_in[7];
    const int*   lambd  = (const int*)d_in[8];
    float* out = (float*)d_out;

    static bool attr_set = false;
    if (!attr_set) {
        cudaFuncSetAttribute(svm_quad_mma_kernel,
                             cudaFuncAttributeMaxDynamicSharedMemorySize, SMEM_BYTES);
        attr_set = true;
    }

    svm_prep_kernel<<<PREP_BLOCKS, 256>>>(x, alpha, xi, y);
    svm_quad_mma_kernel<<<NCHUNKS, 256, SMEM_BYTES>>>(y, coeff, degree);
    svm_fin_kernel<<<1, 1024>>>(b, Cc, lambd, out);
}

// round 17
// speedup vs baseline: 1.4830x; 1.0538x over previous
#include <cuda_runtime.h>
#include <cuda_fp16.h>
#include <cstdint>

#define NN 16384
#define DD 64
#define BLK 128           // tile is BLK x BLK
#define NTILES (NN / BLK) // 128
#define NPAIRS (NTILES * (NTILES + 1) / 2)   // 8256 upper-tri tiles
#define GRID_QUAD 296     // 148 SMs x 2 CTAs: exactly one persistent wave
#define TILES_LO (NPAIRS / GRID_QUAD)        // 27
#define TILES_REM (NPAIRS % GRID_QUAD)       // 264 CTAs get 28
#define PREP_BLOCKS 1024

// ---------------- device scratch (no allocations allowed) ----------------
__device__ float  g_part[NPAIRS];
__device__ float  g_pSa[PREP_BLOCKS], g_pSxi[PREP_BLOCKS], g_pSy[PREP_BLOCKS];
__device__ float  g_w[NN];
__device__ float  g_d2[NN];                     // exact fp32 diag: d_ii = x_i . x_i
__device__ __align__(128) __half g_h[NN * DD];  // fp16 x

// ---------------- helpers ----------------
__device__ __forceinline__ uint32_t smem_u32(const void* p) {
    uint32_t a;
    asm("{ .reg .u64 t; cvta.to.shared.u64 t, %1; cvt.u32.u64 %0, t; }"
        : "=r"(a) : "l"(p));
    return a;
}

#define CP_ASYNC16(dst, src) \
    asm volatile("cp.async.cg.shared.global [%0], [%1], 16;" \
                 :: "r"(dst), "l"(src) : "memory")
#define CP_COMMIT() asm volatile("cp.async.commit_group;" ::: "memory")
#define CP_WAIT0()  asm volatile("cp.async.wait_group 0;" ::: "memory")
#define CP_WAIT1()  asm volatile("cp.async.wait_group 1;" ::: "memory")

__device__ __forceinline__ void ldsm_x4(uint32_t& r0, uint32_t& r1,
                                        uint32_t& r2, uint32_t& r3, uint32_t addr) {
    asm volatile("ldmatrix.sync.aligned.m8n8.x4.shared.b16 {%0,%1,%2,%3}, [%4];"
                 : "=r"(r0), "=r"(r1), "=r"(r2), "=r"(r3) : "r"(addr));
}

__device__ __forceinline__ void mma_f16(float* c, const uint32_t* a, const uint32_t* b) {
    asm volatile(
        "mma.sync.aligned.m16n8k16.row.col.f32.f16.f16.f32 "
        "{%0,%1,%2,%3}, {%4,%5,%6,%7}, {%8,%9}, {%0,%1,%2,%3};"
        : "+f"(c[0]), "+f"(c[1]), "+f"(c[2]), "+f"(c[3])
        : "r"(a[0]), "r"(a[1]), "r"(a[2]), "r"(a[3]), "r"(b[0]), "r"(b[1]));
}

// first-k variant: C = 0 (kills per-tile accumulator zero-init)
__device__ __forceinline__ void mma_f16_z(float* c, const uint32_t* a, const uint32_t* b) {
    asm volatile(
        "mma.sync.aligned.m16n8k16.row.col.f32.f16.f16.f32 "
        "{%0,%1,%2,%3}, {%4,%5,%6,%7}, {%8,%9}, {%10,%10,%10,%10};"
        : "=f"(c[0]), "=f"(c[1]), "=f"(c[2]), "=f"(c[3])
        : "r"(a[0]), "r"(a[1]), "r"(a[2]), "r"(a[3]), "r"(b[0]), "r"(b[1]),
          "f"(0.f));
}

// packed f32x2 ops (PTX ISA 8.6, sm_100+; NOT 'a'-gated)
#define PACK2(d, lo, hi) \
    asm("mov.b64 %0, {%1, %2};" : "=l"(d) : "f"(lo), "f"(hi))
#define UNPACK2(lo, hi, s) \
    asm("mov.b64 {%0, %1}, %2;" : "=f"(lo), "=f"(hi) : "l"(s))
#define ADD2(d, a, b) \
    asm("add.rn.f32x2 %0, %1, %2;" : "=l"(d) : "l"(a), "l"(b))
#define MUL2(d, a, b) \
    asm("mul.rn.f32x2 %0, %1, %2;" : "=l"(d) : "l"(a), "l"(b))
#define FMA2(d, a, b, c) \
    asm("fma.rn.f32x2 %0, %1, %2, %3;" : "=l"(d) : "l"(a), "l"(b), "l"(c))

// scalars may be int32 or float32 bit patterns
__device__ __forceinline__ float scal_as_float(const int* p) {
    int v = *p;
    if (v < 0 || v >= 0x00800000) return __int_as_float(v);
    return (float)v;
}
__device__ __forceinline__ int scal_as_int(const int* p) {
    int v = *p;
    if (v < 0 || v >= 0x00800000) return (int)(__int_as_float(v) + 0.5f);
    return v;
}

// ---------------- prep: fp16 cast + fused exact diag + relu sums --------------
__global__ __launch_bounds__(256)
void svm_prep_kernel(const float* __restrict__ x,
                     const float* __restrict__ alpha,
                     const float* __restrict__ xi,
                     const float* __restrict__ y) {
    const int i = blockIdx.x * 256 + threadIdx.x;

    float s;
    {
        float4 v = ((const float4*)x)[i];
        __half2 h0 = __floats2half2_rn(v.x, v.y);
        __half2 h1 = __floats2half2_rn(v.z, v.w);
        uint2 o;
        o.x = *(const uint32_t*)&h0;
        o.y = *(const uint32_t*)&h1;
        ((uint2*)g_h)[i] = o;
        s = v.x * v.x + v.y * v.y + v.z * v.z + v.w * v.w;
    }
    #pragma unroll
    for (int o = 8; o > 0; o >>= 1)
        s += __shfl_down_sync(0xffffffffu, s, o, 16);
    if ((threadIdx.x & 15) == 0)
        g_d2[i >> 4] = s;

    float a = 0.f, xr = 0.f, yv = 0.f;
    if (i < NN) {
        a  = fmaxf(alpha[i], 0.f);
        xr = fmaxf(xi[i], 0.f);
        yv = y[i];
        g_w[i] = a * yv;
    }
    #pragma unroll
    for (int o = 16; o > 0; o >>= 1) {
        a  += __shfl_down_sync(0xffffffffu, a,  o);
        xr += __shfl_down_sync(0xffffffffu, xr, o);
        yv += __shfl_down_sync(0xffffffffu, yv, o);
    }
    __shared__ float rA[8], rX[8], rY[8];
    int wid = threadIdx.x >> 5, lid = threadIdx.x & 31;
    if (lid == 0) { rA[wid] = a; rX[wid] = xr; rY[wid] = yv; }
    __syncthreads();
    if (threadIdx.x == 0) {
        float sa = 0.f, sx = 0.f, sy = 0.f;
        #pragma unroll
        for (int w = 0; w < 8; ++w) { sa += rA[w]; sx += rX[w]; sy += rY[w]; }
        g_pSa[blockIdx.x]  = sa;
        g_pSxi[blockIdx.x] = sx;
        g_pSy[blockIdx.x]  = sy;
    }
}

// ---------------- main Gram kernel: persistent CTAs, double-buffered ----------
// Identical per-tile structure to the proven R10/R15 loop; only the tile
// distribution changed (one persistent wave, contiguous ranges).
#define BUF_STRIDE 32768
#define OFF_VEC    65536
#define VEC_STRIDE 2560
#define SMEM_BYTES (65536 + 2 * VEC_STRIDE + 256)

__global__ __launch_bounds__(256, 2)
void svm_quad_mma_kernel(const float* __restrict__ y,
                         const int* __restrict__ coeff_p,
                         const int* __restrict__ degree_p) {
    extern __shared__ char smem_raw[];
    const uint32_t raw = smem_u32(smem_raw);
    const uint32_t base = (raw + 127u) & ~127u;
    char* smem = smem_raw + (base - raw);

    const int tid = threadIdx.x;
    const int wid = tid >> 5;
    const int lid = tid & 31;
    const int wm  = wid & 3;
    const int wn  = wid >> 2;

    // ---- persistent work range: contiguous tiles [idx0, idx0+ntile) ----
    const int k = blockIdx.x;
    const int idx0 = k * TILES_LO + (k < TILES_REM ? k : TILES_REM);
    const int ntile = TILES_LO + (k < TILES_REM ? 1 : 0);

    // ---- triangular decode of first tile ----
    int I = (int)((2.0 * NTILES + 1.0
                   - sqrt((2.0 * NTILES + 1.0) * (2.0 * NTILES + 1.0) - 8.0 * idx0)) * 0.5);
    if (I > NTILES - 1) I = NTILES - 1;
    if (I < 0) I = 0;
    #pragma unroll 1
    while (I > 0 && (I * NTILES - (I * (I - 1)) / 2) > idx0) --I;
    #pragma unroll 1
    while (((I + 1) * NTILES - ((I + 1) * I) / 2) <= idx0) ++I;
    int J = I + (idx0 - (I * NTILES - (I * (I - 1)) / 2));

    #define PREFETCH(I_, J_, cur_) do {                                          \
        const int pbi = (I_) * BLK, pbj = (J_) * BLK;                            \
        const char* srcA = (const char*)(g_h + (size_t)pbi * DD);                \
        const char* srcB = (const char*)(g_h + (size_t)pbj * DD);                \
        const uint32_t dA = base + (cur_) * BUF_STRIDE;                          \
        const uint32_t dB = dA + 16384;                                          \
        _Pragma("unroll")                                                        \
        for (int it = 0; it < 4; ++it) {                                         \
            int i2 = tid + it * 256;                                             \
            int row = i2 >> 3, c16 = i2 & 7;                                     \
            int sw = row * 128 + ((c16 ^ (row & 7)) << 4);                       \
            int lin = i2 * 16;                                                   \
            CP_ASYNC16(dA + sw, srcA + lin);                                     \
            CP_ASYNC16(dB + sw, srcB + lin);                                     \
        }                                                                        \
        if (tid < 160) {                                                         \
            const uint32_t dv = base + OFF_VEC + (cur_) * VEC_STRIDE;            \
            int v = tid >> 5, c = tid & 31;                                      \
            const float* vsrc;                                                   \
            if      (v == 0) vsrc = g_w  + pbj;                                  \
            else if (v == 1) vsrc = y    + pbj;                                  \
            else if (v == 2) vsrc = g_w  + pbi;                                  \
            else if (v == 3) vsrc = y    + pbi;                                  \
            else             vsrc = g_d2 + pbi;                                  \
            CP_ASYNC16(dv + v * 512 + c * 16, (const char*)(vsrc) + c * 16);     \
        }                                                                        \
        CP_COMMIT();                                                             \
    } while (0)

    PREFETCH(I, J, 0);

    const int q   = lid >> 3;
    const int seg = lid & 7;
    const int rowA0 = wm * 32 + seg + ((q & 1) << 3);
    const int chA   = q >> 1;
    const int rowB0 = wn * 64 + seg + ((q >> 1) << 3);
    const int chB   = q & 1;
    const int rBase = wm * 32 + (lid >> 2);
    const int cBase = wn * 64 + 2 * (lid & 3);

    const float coeff = scal_as_float(coeff_p);
    const int   deg   = scal_as_int(degree_p);
    uint64_t coeff2;
    PACK2(coeff2, coeff, coeff);

    #pragma unroll 1
    for (int t = 0; t < ntile; ++t) {
        const int cur = t & 1;
        const bool offdiag = (I != J);

        int In = I, Jn = J + 1;
        if (Jn == NTILES) { ++In; Jn = In; }
        if (t + 1 < ntile) {
            PREFETCH(In, Jn, 1 - cur);
            CP_WAIT1();
        } else {
            CP_WAIT0();
        }
        __syncthreads();

        const uint32_t aB = base + cur * BUF_STRIDE;
        const uint32_t bB = aB + 16384;
        const char* vecp = smem + OFF_VEC + cur * VEC_STRIDE;
        const float* s_wJ = (const float*)(vecp);
        const float* s_yJ = (const float*)(vecp + 512);
        const float* s_wI = (const float*)(vecp + 1024);
        const float* s_yI = (const float*)(vecp + 1536);
        const float* s_d2 = (const float*)(vecp + 2048);

        float accf[2][8][4];

        // ---- mainloop: single fp16 pass, K=64; ks=0 writes C=0 ----
        #pragma unroll
        for (int ks = 0; ks < 4; ++ks) {
            uint32_t af[2][4];
            #pragma unroll
            for (int am = 0; am < 2; ++am) {
                int row = rowA0 + am * 16;
                int ch  = (chA + 2 * ks) ^ (row & 7);
                ldsm_x4(af[am][0], af[am][1], af[am][2], af[am][3],
                        aB + row * 128 + (ch << 4));
            }
            uint32_t bf[8][2];
            #pragma unroll
            for (int bn2 = 0; bn2 < 4; ++bn2) {
                int row = rowB0 + bn2 * 16;
                int ch  = (chB + 2 * ks) ^ (row & 7);
                ldsm_x4(bf[bn2 * 2][0], bf[bn2 * 2][1],
                        bf[bn2 * 2 + 1][0], bf[bn2 * 2 + 1][1],
                        bB + row * 128 + (ch << 4));
            }
            if (ks == 0) {
                #pragma unroll
                for (int am = 0; am < 2; ++am)
                    #pragma unroll
                    for (int bn = 0; bn < 8; ++bn)
                        mma_f16_z(accf[am][bn], af[am], bf[bn]);
            } else {
                #pragma unroll
                for (int am = 0; am < 2; ++am)
                    #pragma unroll
                    for (int bn = 0; bn < 8; ++bn)
                        mma_f16(accf[am][bn], af[am], bf[bn]);
            }
        }

        // ---- exact diagonal patch (diag tiles only) ----
        if (!offdiag) {
            #pragma unroll
            for (int am = 0; am < 2; ++am)
                #pragma unroll
                for (int bn = 0; bn < 8; ++bn)
                    #pragma unroll
                    for (int r = 0; r < 4; ++r) {
                        int rl = rBase + am * 16 + ((r >> 1) << 3);
                        int cl = cBase + bn * 8 + (r & 1);
                        if (rl == cl) accf[am][bn][r] = s_d2[rl];
                    }
        }

        // ---- epilogue (packed f32x2 for deg==3 fast path) ----
        float part = 0.f;
        #pragma unroll
        for (int am = 0; am < 2; ++am) {
            const int r0i = rBase + am * 16;
            const float yr0 = s_yI[r0i],     yr1 = s_yI[r0i + 8];
            const float wr0 = s_wI[r0i],     wr1 = s_wI[r0i + 8];
            if (deg == 3) {
                uint64_t S0w = 0, S1w = 0, S0y = 0, S1y = 0;
                #pragma unroll
                for (int bn = 0; bn < 8; ++bn) {
                    const int c0i = cBase + bn * 8;
                    const uint64_t W01 = *(const uint64_t*)(s_wJ + c0i);
                    const uint64_t Y01 = *(const uint64_t*)(s_yJ + c0i);
                    uint64_t k01, k23, p, q01, q23;
                    PACK2(k01, accf[am][bn][0], accf[am][bn][1]);
                    PACK2(k23, accf[am][bn][2], accf[am][bn][3]);
                    ADD2(k01, k01, coeff2);
                    ADD2(k23, k23, coeff2);
                    MUL2(p, k01, k01);  MUL2(q01, p, k01);
                    MUL2(p, k23, k23);  MUL2(q23, p, k23);
                    FMA2(S0w, W01, q01, S0w);
                    FMA2(S1w, W01, q23, S1w);
                    FMA2(S0y, Y01, q01, S0y);
                    FMA2(S1y, Y01, q23, S1y);
                }
                float a0, a1;
                UNPACK2(a0, a1, S0w); float s0w = a0 + a1;
                UNPACK2(a0, a1, S1w); float s1w = a0 + a1;
                part = fmaf(yr0, s0w, part);
                part = fmaf(yr1, s1w, part);
                if (offdiag) {
                    UNPACK2(a0, a1, S0y); float s0y = a0 + a1;
                    UNPACK2(a0, a1, S1y); float s1y = a0 + a1;
                    part = fmaf(wr0, s0y, part);
                    part = fmaf(wr1, s1y, part);
                }
            } else {
                float s0w = 0.f, s1w = 0.f, s0y = 0.f, s1y = 0.f;
                #pragma unroll
                for (int bn = 0; bn < 8; ++bn) {
                    const int c0i = cBase + bn * 8;
                    const float wc0 = s_wJ[c0i], wc1 = s_wJ[c0i + 1];
                    const float yc0 = s_yJ[c0i], yc1 = s_yJ[c0i + 1];
                    float kk[4];
                    #pragma unroll
                    for (int r = 0; r < 4; ++r) {
                        float v = accf[am][bn][r] + coeff;
                        float p = 1.f;
                        for (int d = 0; d < deg; ++d) p *= v;
                        kk[r] = p;
                    }
                    s0w = fmaf(wc0, kk[0], s0w); s0w = fmaf(wc1, kk[1], s0w);
                    s1w = fmaf(wc0, kk[2], s1w); s1w = fmaf(wc1, kk[3], s1w);
                    s0y = fmaf(yc0, kk[0], s0y); s0y = fmaf(yc1, kk[1], s0y);
                    s1y = fmaf(yc0, kk[2], s1y); s1y = fmaf(yc1, kk[3], s1y);
                }
                part = fmaf(yr0, s0w, part);
                part = fmaf(yr1, s1w, part);
                if (offdiag) {
                    part = fmaf(wr0, s0y, part);
                    part = fmaf(wr1, s1y, part);
                }
            }
        }

        // ---- block reduce -> per-tile partial (R10 structure) ----
        #pragma unroll
        for (int o = 16; o > 0; o >>= 1)
            part += __shfl_down_sync(0xffffffffu, part, o);
        __shared__ float red[8];
        if (lid == 0) red[wid] = part;
        __syncthreads();   // protects red[] AND buffer reads before next refill
        if (tid == 0) {
            float s = 0.f;
            #pragma unroll
            for (int w = 0; w < 8; ++w) s += red[w];
            g_part[idx0 + t] = s;
        }
        I = In; J = Jn;
    }
    #undef PREFETCH
}

// ---------------- final reduction + loss ----------------
__global__ __launch_bounds__(1024)
void svm_fin_kernel(const float* __restrict__ b,
                    const int*   __restrict__ C_p,
                    const int*   __restrict__ lambd_p,
                    float* __restrict__ out) {
    const int tid = threadIdx.x;
    double q = 0.0;
    for (int i = tid; i < NPAIRS; i += 1024) q += (double)g_part[i];
    double sa = 0.0, sx = 0.0, sy = 0.0;
    if (tid < PREP_BLOCKS) {
        sa = (double)g_pSa[tid];
        sx = (double)g_pSxi[tid];
        sy = (double)g_pSy[tid];
    }
    #pragma unroll
    for (int o = 16; o > 0; o >>= 1) {
        q  += __shfl_down_sync(0xffffffffu, q,  o);
        sa += __shfl_down_sync(0xffffffffu, sa, o);
        sx += __shfl_down_sync(0xffffffffu, sx, o);
        sy += __shfl_down_sync(0xffffffffu, sy, o);
    }
    __shared__ double rq[32], ra[32], rx[32], ry[32];
    int wid = tid >> 5, lid = tid & 31;
    if (lid == 0) { rq[wid] = q; ra[wid] = sa; rx[wid] = sx; ry[wid] = sy; }
    __syncthreads();
    if (tid == 0) {
        double Q = 0, Sa = 0, Sxi = 0, Sy = 0;
        #pragma unroll
        for (int w = 0; w < 32; ++w) {
            Q += rq[w]; Sa += ra[w]; Sxi += rx[w]; Sy += ry[w];
        }
        double C  = (double)scal_as_float(C_p);
        double la = (double)scal_as_float(lambd_p);
        double loss = 0.5 * Sa + C * Sxi
                    + la * ((Q + (double)b[0] * Sy + Sxi) / (double)NN - 1.0);
        out[0] = (float)loss;
    }
}

// ---------------- launch ----------------
extern "C" void kernel_launch(void* const* d_in, const int* in_sizes, int n_in,
                              void* d_out, int out_size) {
    const float* x      = (const float*)d_in[0];
    const float* y      = (const float*)d_in[1];
    const float* alpha  = (const float*)d_in[2];
    const float* xi     = (const float*)d_in[3];
    const float* b      = (const float*)d_in[4];
    const int*   coeff  = (const int*)d_in[5];
    const int*   degree = (const int*)d_in[6];
    const int*   Cc     = (const int*)d_in[7];
    const int*   lambd  = (const int*)d_in[8];
    float* out = (float*)d_out;

    static bool attr_set = false;
    if (!attr_set) {
        cudaFuncSetAttribute(svm_quad_mma_kernel,
                             cudaFuncAttributeMaxDynamicSharedMemorySize, SMEM_BYTES);
        attr_set = true;
    }

    svm_prep_kernel<<<PREP_BLOCKS, 256>>>(x, alpha, xi, y);
    svm_quad_mma_kernel<<<GRID_QUAD, 256, SMEM_BYTES>>>(y, coeff, degree);
    svm_fin_kernel<<<1, 1024>>>(b, Cc, lambd, out);
}